// round 16
// baseline (speedup 1.0000x reference)
#include <cuda_runtime.h>
#include <cuda_bf16.h>
#include <cuda_fp8.h>
#include <math.h>

#define LNUM 4
#define DIM 256
#define NH 8
#define MLP 1024
#define BATCH 8
#define SEQ 1024
#define HID 2048            // NH * DIM
#define ROWS (BATCH*SEQ)    // 8192
#define BH (BATCH*NH)       // 64

// ---------------- scratch (device globals; no allocation allowed) ----------------
__device__ __nv_bfloat16 g_h[ROWS*DIM];              // LN output
__device__ unsigned char g_q[BH*SEQ*DIM];            // q fp8 [b,h,n,d]
__device__ unsigned char g_k[BH*SEQ*DIM];            // k fp8 [b,h,n,d]
__device__ unsigned char g_v[BH*DIM*SEQ];            // v fp8 TRANSPOSED [b,h,d,n]
__device__ unsigned char g_s[(size_t)BH*SEQ*SEQ];    // P = e4m3(exp(s)/64) [bh][q][k]
__device__ float         g_rs[BH*SEQ];               // attention row sums (fp32, exact)
__device__ __nv_bfloat16 g_o[(size_t)ROWS*HID];      // attn out [b,n,h*d]
__device__ __nv_bfloat16 g_m[ROWS*MLP];              // mlp hidden
// transposed bf16 weights: [N][K]; qkv additionally de-interleaved (si-major)
__device__ __nv_bfloat16 g_qkvw[LNUM*DIM*3*HID];
__device__ __nv_bfloat16 g_projw[LNUM*HID*DIM];
__device__ __nv_bfloat16 g_w1[LNUM*DIM*MLP];
__device__ __nv_bfloat16 g_w2[LNUM*MLP*DIM];

// ---------------- weight preprocess: transpose [K][N] -> [N][K], cvt bf16 -------
__global__ void wtrans_kernel(const float* __restrict__ src, __nv_bfloat16* __restrict__ dst,
                              int K, int N)
{
    __shared__ float tile[32][33];
    long zo = (long)blockIdx.z * K * N;
    int k0 = blockIdx.y * 32, n0 = blockIdx.x * 32;
    for (int i = threadIdx.y; i < 32; i += 8)
        tile[i][threadIdx.x] = src[zo + (long)(k0 + i)*N + n0 + threadIdx.x];
    __syncthreads();
    int k = k0 + threadIdx.x;
    for (int i = threadIdx.y; i < 32; i += 8)
        dst[zo + (long)(n0 + i)*K + k] = __float2bfloat16(tile[threadIdx.x][i]);
}

// qkv variant: de-interleave columns: n_new = si*HID + h*DIM + dc
__global__ void wtrans_qkv_kernel(const float* __restrict__ src, __nv_bfloat16* __restrict__ dst)
{
    __shared__ float tile[32][33];
    const int K = DIM, N = 3*HID;
    long zo = (long)blockIdx.z * K * N;
    int k0 = blockIdx.y * 32, n0 = blockIdx.x * 32;
    for (int i = threadIdx.y; i < 32; i += 8)
        tile[i][threadIdx.x] = src[zo + (long)(k0 + i)*N + n0 + threadIdx.x];
    __syncthreads();
    int k = k0 + threadIdx.x;
    for (int i = threadIdx.y; i < 32; i += 8) {
        int n_old = n0 + i;
        int si = n_old % 3, dc = (n_old / 3) & (DIM - 1), h = n_old / (3*DIM);
        long n_new = (long)si*HID + h*DIM + dc;
        dst[zo + n_new*K + k] = __float2bfloat16(tile[threadIdx.x][i]);
    }
}

// ---------------- LayerNorm: warp per row, 8 rows/block, vectorized -------------
__global__ void ln_kernel(const float* __restrict__ x, const float* __restrict__ g,
                          const float* __restrict__ b, __nv_bfloat16* __restrict__ out)
{
    int lane = threadIdx.x & 31;
    long row = (long)blockIdx.x*8 + (threadIdx.x >> 5);
    const float4* xp = (const float4*)(x + row*DIM);
    float4 a0 = xp[lane*2], a1 = xp[lane*2 + 1];
    float s1 = a0.x + a0.y + a0.z + a0.w + a1.x + a1.y + a1.z + a1.w;
    float s2 = a0.x*a0.x + a0.y*a0.y + a0.z*a0.z + a0.w*a0.w
             + a1.x*a1.x + a1.y*a1.y + a1.z*a1.z + a1.w*a1.w;
    #pragma unroll
    for (int o = 16; o > 0; o >>= 1) {
        s1 += __shfl_xor_sync(0xffffffffu, s1, o);
        s2 += __shfl_xor_sync(0xffffffffu, s2, o);
    }
    float m = s1 * (1.0f/DIM);
    float rstd = rsqrtf(s2 * (1.0f/DIM) - m*m + 1e-5f);
    float4 g0 = ((const float4*)g)[lane*2], g1 = ((const float4*)g)[lane*2 + 1];
    float4 b0 = ((const float4*)b)[lane*2], b1 = ((const float4*)b)[lane*2 + 1];
    __nv_bfloat162 r[4];
    r[0].x = __float2bfloat16((a0.x - m)*rstd*g0.x + b0.x);
    r[0].y = __float2bfloat16((a0.y - m)*rstd*g0.y + b0.y);
    r[1].x = __float2bfloat16((a0.z - m)*rstd*g0.z + b0.z);
    r[1].y = __float2bfloat16((a0.w - m)*rstd*g0.w + b0.w);
    r[2].x = __float2bfloat16((a1.x - m)*rstd*g1.x + b1.x);
    r[2].y = __float2bfloat16((a1.y - m)*rstd*g1.y + b1.y);
    r[3].x = __float2bfloat16((a1.z - m)*rstd*g1.z + b1.z);
    r[3].y = __float2bfloat16((a1.w - m)*rstd*g1.w + b1.w);
    ((uint4*)(out + row*DIM))[lane] = *(uint4*)r;
}

// ---------------- MMA / cp.async / ldmatrix helpers ----------------
__device__ __forceinline__ void mma_bf16(float* d, unsigned a0, unsigned a1, unsigned a2,
                                         unsigned a3, unsigned b0, unsigned b1) {
    asm volatile(
        "mma.sync.aligned.m16n8k16.row.col.f32.bf16.bf16.f32 "
        "{%0,%1,%2,%3}, {%4,%5,%6,%7}, {%8,%9}, {%0,%1,%2,%3};"
        : "+f"(d[0]), "+f"(d[1]), "+f"(d[2]), "+f"(d[3])
        : "r"(a0), "r"(a1), "r"(a2), "r"(a3), "r"(b0), "r"(b1));
}
__device__ __forceinline__ void mma_e4m3(float* d, unsigned a0, unsigned a1, unsigned a2,
                                         unsigned a3, unsigned b0, unsigned b1) {
    asm volatile(
        "mma.sync.aligned.m16n8k32.row.col.f32.e4m3.e4m3.f32 "
        "{%0,%1,%2,%3}, {%4,%5,%6,%7}, {%8,%9}, {%0,%1,%2,%3};"
        : "+f"(d[0]), "+f"(d[1]), "+f"(d[2]), "+f"(d[3])
        : "r"(a0), "r"(a1), "r"(a2), "r"(a3), "r"(b0), "r"(b1));
}
__device__ __forceinline__ void cpa16(unsigned d, const void* s) {
    asm volatile("cp.async.ca.shared.global [%0], [%1], 16;" :: "r"(d), "l"(s));
}
__device__ __forceinline__ void ldsm_x4(unsigned* r, unsigned a) {
    asm volatile("ldmatrix.sync.aligned.m8n8.x4.shared.b16 {%0,%1,%2,%3}, [%4];"
        : "=r"(r[0]), "=r"(r[1]), "=r"(r[2]), "=r"(r[3]) : "r"(a));
}
__device__ __forceinline__ unsigned short f2e4m3x2(float lo, float hi) {
    unsigned short r;
    asm("cvt.rn.satfinite.e4m3x2.f32 %0, %1, %2;" : "=h"(r) : "f"(hi), "f"(lo));
    return r;
}
__device__ __forceinline__ unsigned char f2e4m3(float v) {
    return (unsigned char)(f2e4m3x2(v, 0.f) & 0xFF);
}

enum { EPI_QKV = 0, EPI_EXPSTORE = 1, EPI_OSCAT = 2, EPI_RES = 3, EPI_GELU = 4 };

#define BKS 80             // bytes per staged row (64B data + 16B pad): LDSM conflict-free
#define NSTG 3
#define BSTGB (128*BKS)    // B stage bytes (always 128 n-rows)
#define VST 144            // fp8 epilogue staging row stride (16-aligned)

// GSMEM per NMT: NSTG*(A + B) where A = 64*NMT*BKS
#define GSMEM2 (NSTG*(128*BKS + BSTGB))   // 61440
#define GSMEM1 (NSTG*(64*BKS + BSTGB))    // 46080

// ================================================================================
// bf16 TC GEMM: block (64*NMT)x128, 256 thr, warp (16*NMT)x64.
// ================================================================================
template<int EPI, int NMT>
__global__ __launch_bounds__(256, 2)
void gemm_bf(const __nv_bfloat16* __restrict__ A, const __nv_bfloat16* __restrict__ Bm,
             const float* __restrict__ bias, void* __restrict__ Cp,
             void* __restrict__ P1, void* __restrict__ P2, float* __restrict__ RS,
             int Nc, int K, int ldk, long sA, long sB, long sC)
{
    extern __shared__ char dsm[];
    constexpr int MB = 64*NMT;            // m rows per block
    constexpr unsigned ASTGv = MB*BKS;    // A stage bytes

    int z  = blockIdx.z;
    int m0 = blockIdx.y * MB;
    int n0 = blockIdx.x * 128;
    int t    = threadIdx.x;
    int lane = t & 31;
    int warp = t >> 5;
    int wm = (warp >> 1) * (16*NMT);
    int wn = (warp & 1) * 64;
    int gid = lane >> 2;
    int tig = lane & 3;

    // A loader: MB rows x 64B; NMT==2: 2 thr/row x 32B; NMT==1: 4 thr/row x 16B
    int lrA = (NMT == 2) ? (t >> 1) : (t >> 2);
    int laB = (NMT == 2) ? ((t & 1)*32) : ((t & 3)*16);
    const __nv_bfloat16* apg = A + z*sA + (long)(m0 + lrA)*ldk + laB/2;
    int lrB = t >> 1;
    const __nv_bfloat16* bpg = Bm + z*sB + (long)(n0 + lrB)*ldk + (t & 1)*16;
    unsigned asb = (unsigned)__cvta_generic_to_shared(dsm);
    unsigned bsb = asb + NSTG*ASTGv;
    unsigned adl = asb + (unsigned)(lrA*BKS + laB);
    unsigned bdl = bsb + (unsigned)(lrB*BKS + (t & 1)*32);

    int lm = lane >> 3, ls = lane & 7;
    unsigned lro = (unsigned)(((lm & 1)*8 + ls)*BKS + (lm >> 1)*16);
    unsigned abase = asb + (unsigned)(wm*BKS) + lro;
    unsigned bbase = bsb + (unsigned)(wn*BKS) + lro;

    float acc[NMT][8][4];
    #pragma unroll
    for (int mt = 0; mt < NMT; mt++)
        #pragma unroll
        for (int nt = 0; nt < 8; nt++)
            #pragma unroll
            for (int p = 0; p < 4; p++) acc[mt][nt][p] = 0.f;

    int niter = K / 32;
    #pragma unroll
    for (int pi = 0; pi < 2; pi++) {
        int k0 = pi * 32;
        unsigned ao = (unsigned)pi*ASTGv, bo = (unsigned)pi*BSTGB;
        cpa16(adl + ao, apg + k0);
        if (NMT == 2) cpa16(adl + ao + 16, apg + k0 + 8);
        cpa16(bdl + bo, bpg + k0);  cpa16(bdl + bo + 16, bpg + k0 + 8);
        asm volatile("cp.async.commit_group;");
    }

    int st = 0;
    for (int iter = 0; iter < niter; iter++) {
        if (iter + 1 < niter) asm volatile("cp.async.wait_group 1;");
        else                  asm volatile("cp.async.wait_group 0;");
        __syncthreads();

        if (iter + 2 < niter) {
            int k0 = (iter + 2) * 32;
            int ws = st + 2; if (ws >= NSTG) ws -= NSTG;
            unsigned ao = (unsigned)ws*ASTGv, bo = (unsigned)ws*BSTGB;
            cpa16(adl + ao, apg + k0);
            if (NMT == 2) cpa16(adl + ao + 16, apg + k0 + 8);
            cpa16(bdl + bo, bpg + k0);  cpa16(bdl + bo + 16, bpg + k0 + 8);
            asm volatile("cp.async.commit_group;");
        }

        unsigned soA = (unsigned)st*ASTGv, soB = (unsigned)st*BSTGB;
        #pragma unroll
        for (int kh = 0; kh < 2; kh++) {
            unsigned af[NMT][4], bq[4][4];
            #pragma unroll
            for (int mt = 0; mt < NMT; mt++)
                ldsm_x4(af[mt], abase + soA + (unsigned)(mt*16*BKS + kh*32));
            #pragma unroll
            for (int p = 0; p < 4; p++)
                ldsm_x4(bq[p], bbase + soB + (unsigned)(p*16*BKS + kh*32));
            #pragma unroll
            for (int mt = 0; mt < NMT; mt++)
                #pragma unroll
                for (int p = 0; p < 4; p++) {
                    mma_bf16(acc[mt][2*p],   af[mt][0], af[mt][1], af[mt][2], af[mt][3],
                             bq[p][0], bq[p][2]);
                    mma_bf16(acc[mt][2*p+1], af[mt][0], af[mt][1], af[mt][2], af[mt][3],
                             bq[p][1], bq[p][3]);
                }
        }
        st++; if (st >= NSTG) st = 0;
    }

    // ---------------- epilogues ----------------
    if (EPI == EPI_QKV) {      // only instantiated with NMT==2
        int si  = n0 / HID;
        int hh  = (n0 % HID) / DIM;
        int dc0 = n0 % DIM;
        int b_ = m0 >> 10;
        long bh = (long)b_*NH + hh;
        unsigned char* stg = (unsigned char*)dsm;
        __syncthreads();
        if (si < 2) {
            #pragma unroll
            for (int mt = 0; mt < NMT; mt++) {
                int rl = wm + mt*16 + gid;
                #pragma unroll
                for (int nt = 0; nt < 8; nt++) {
                    int cl = wn + nt*8 + 2*tig;
                    int dc = dc0 + cl;
                    float bb0 = bias[hh*3*DIM + dc*3 + si];
                    float bb1 = bias[hh*3*DIM + (dc+1)*3 + si];
                    *(unsigned short*)&stg[rl*VST + cl] =
                        f2e4m3x2(acc[mt][nt][0] + bb0, acc[mt][nt][1] + bb1);
                    *(unsigned short*)&stg[(rl+8)*VST + cl] =
                        f2e4m3x2(acc[mt][nt][2] + bb0, acc[mt][nt][3] + bb1);
                }
            }
            __syncthreads();
            unsigned char* dst = (unsigned char*)((si == 0) ? Cp : P1);
            int rl = t >> 1, hf = t & 1;
            int n1 = (m0 + rl) & (SEQ - 1);
            const uint4* src = (const uint4*)(stg + rl*VST + hf*64);
            uint4* dq = (uint4*)&dst[(bh*SEQ + n1)*DIM + dc0 + hf*64];
            dq[0] = src[0]; dq[1] = src[1]; dq[2] = src[2]; dq[3] = src[3];
        } else {
            #pragma unroll
            for (int mt = 0; mt < NMT; mt++) {
                int rl = wm + mt*16 + gid;
                #pragma unroll
                for (int nt = 0; nt < 8; nt++) {
                    int cl = wn + nt*8 + 2*tig;
                    int dc = dc0 + cl;
                    float bb0 = bias[hh*3*DIM + dc*3 + 2];
                    float bb1 = bias[hh*3*DIM + (dc+1)*3 + 2];
                    stg[cl*VST + rl]         = f2e4m3(acc[mt][nt][0] + bb0);
                    stg[(cl+1)*VST + rl]     = f2e4m3(acc[mt][nt][1] + bb1);
                    stg[cl*VST + rl + 8]     = f2e4m3(acc[mt][nt][2] + bb0);
                    stg[(cl+1)*VST + rl + 8] = f2e4m3(acc[mt][nt][3] + bb1);
                }
            }
            __syncthreads();
            int nb = m0 & (SEQ - 1);
            int dcr = t >> 1, hf = t & 1;
            const uint4* src = (const uint4*)(stg + dcr*VST + hf*64);
            uint4* dstv = (uint4*)&((unsigned char*)P2)[(bh*DIM + dc0 + dcr)*SEQ + nb + hf*64];
            dstv[0] = src[0]; dstv[1] = src[1]; dstv[2] = src[2]; dstv[3] = src[3];
        }
        return;
    }

    #pragma unroll
    for (int mt = 0; mt < NMT; mt++) {
        #pragma unroll
        for (int nt = 0; nt < 8; nt++) {
            int r0 = m0 + wm + mt*16 + gid;
            int col = n0 + wn + nt*8 + 2*tig;
            if (EPI == EPI_RES) {
                #pragma unroll
                for (int p = 0; p < 4; p++) {
                    int row = r0 + ((p >= 2) ? 8 : 0);
                    int cc = col + (p & 1);
                    float add = acc[mt][nt][p] + ((z == 0) ? bias[cc] : 0.f);
                    atomicAdd(&((float*)Cp)[(long)row*Nc + cc], add);
                }
            } else {   // EPI_GELU: packed bf162 stores
                float u0 = acc[mt][nt][0] + bias[col];
                float u1 = acc[mt][nt][1] + bias[col+1];
                float u2 = acc[mt][nt][2] + bias[col];
                float u3 = acc[mt][nt][3] + bias[col+1];
                __nv_bfloat162 lo, hi;
                lo.x = __float2bfloat16(0.5f*u0*(1.0f + erff(u0*0.70710678118654752f)));
                lo.y = __float2bfloat16(0.5f*u1*(1.0f + erff(u1*0.70710678118654752f)));
                hi.x = __float2bfloat16(0.5f*u2*(1.0f + erff(u2*0.70710678118654752f)));
                hi.y = __float2bfloat16(0.5f*u3*(1.0f + erff(u3*0.70710678118654752f)));
                *(__nv_bfloat162*)&((__nv_bfloat16*)Cp)[(long)r0*Nc + col]     = lo;
                *(__nv_bfloat162*)&((__nv_bfloat16*)Cp)[(long)(r0+8)*Nc + col] = hi;
            }
        }
    }
}

// ================================================================================
// FP8 TC GEMM: block (64*NMT)x128, m16n8k32.
// ================================================================================
template<int EPI, int NMT>
__global__ __launch_bounds__(256, 2)
void gemm_f8(const unsigned char* __restrict__ A, const unsigned char* __restrict__ Bm,
             void* __restrict__ Cp, float* __restrict__ RS,
             int Nc, int K, int ldk, long sA, long sB, long sC)
{
    extern __shared__ char dsm[];
    constexpr int MB = 64*NMT;
    constexpr unsigned ASTGv = MB*BKS;

    int z  = blockIdx.z;
    int m0 = blockIdx.y * MB;
    int n0 = blockIdx.x * 128;
    int t    = threadIdx.x;
    int lane = t & 31;
    int warp = t >> 5;
    int wm = (warp >> 1) * (16*NMT);
    int wn = (warp & 1) * 64;
    int gid = lane >> 2;
    int tig = lane & 3;

    int lrA = (NMT == 2) ? (t >> 1) : (t >> 2);
    int laB = (NMT == 2) ? ((t & 1)*32) : ((t & 3)*16);
    const unsigned char* apg = A + z*sA + (long)(m0 + lrA)*ldk + laB;
    int lrB = t >> 1;
    const unsigned char* bpg = Bm + z*sB + (long)(n0 + lrB)*ldk + (t & 1)*32;
    unsigned asb = (unsigned)__cvta_generic_to_shared(dsm);
    unsigned bsb = asb + NSTG*ASTGv;
    unsigned adl = asb + (unsigned)(lrA*BKS + laB);
    unsigned bdl = bsb + (unsigned)(lrB*BKS + (t & 1)*32);

    int lm = lane >> 3, ls = lane & 7;
    unsigned lro = (unsigned)(((lm & 1)*8 + ls)*BKS + (lm >> 1)*16);
    unsigned abase = asb + (unsigned)(wm*BKS) + lro;
    unsigned bbase = bsb + (unsigned)(wn*BKS) + lro;

    float acc[NMT][8][4];
    #pragma unroll
    for (int mt = 0; mt < NMT; mt++)
        #pragma unroll
        for (int nt = 0; nt < 8; nt++)
            #pragma unroll
            for (int p = 0; p < 4; p++) acc[mt][nt][p] = 0.f;

    int niter = K / 64;
    #pragma unroll
    for (int pi = 0; pi < 2; pi++) {
        int k0 = pi * 64;
        unsigned ao = (unsigned)pi*ASTGv, bo = (unsigned)pi*BSTGB;
        cpa16(adl + ao, apg + k0);
        if (NMT == 2) cpa16(adl + ao + 16, apg + k0 + 16);
        cpa16(bdl + bo, bpg + k0);  cpa16(bdl + bo + 16, bpg + k0 + 16);
        asm volatile("cp.async.commit_group;");
    }

    int st = 0;
    for (int iter = 0; iter < niter; iter++) {
        if (iter + 1 < niter) asm volatile("cp.async.wait_group 1;");
        else                  asm volatile("cp.async.wait_group 0;");
        __syncthreads();

        if (iter + 2 < niter) {
            int k0 = (iter + 2) * 64;
            int ws = st + 2; if (ws >= NSTG) ws -= NSTG;
            unsigned ao = (unsigned)ws*ASTGv, bo = (unsigned)ws*BSTGB;
            cpa16(adl + ao, apg + k0);
            if (NMT == 2) cpa16(adl + ao + 16, apg + k0 + 16);
            cpa16(bdl + bo, bpg + k0);  cpa16(bdl + bo + 16, bpg + k0 + 16);
            asm volatile("cp.async.commit_group;");
        }

        unsigned soA = (unsigned)st*ASTGv, soB = (unsigned)st*BSTGB;
        #pragma unroll
        for (int kh = 0; kh < 2; kh++) {
            unsigned af[NMT][4], bq[4][4];
            #pragma unroll
            for (int mt = 0; mt < NMT; mt++)
                ldsm_x4(af[mt], abase + soA + (unsigned)(mt*16*BKS + kh*32));
            #pragma unroll
            for (int p = 0; p < 4; p++)
                ldsm_x4(bq[p], bbase + soB + (unsigned)(p*16*BKS + kh*32));
            #pragma unroll
            for (int mt = 0; mt < NMT; mt++)
                #pragma unroll
                for (int p = 0; p < 4; p++) {
                    mma_e4m3(acc[mt][2*p],   af[mt][0], af[mt][1], af[mt][2], af[mt][3],
                             bq[p][0], bq[p][2]);
                    mma_e4m3(acc[mt][2*p+1], af[mt][0], af[mt][1], af[mt][2], af[mt][3],
                             bq[p][1], bq[p][3]);
                }
        }
        st++; if (st >= NSTG) st = 0;
    }

    if (EPI == EPI_EXPSTORE) {   // only instantiated with NMT==2
        unsigned char* stg = (unsigned char*)dsm;
        float ls2[NMT][2];
        #pragma unroll
        for (int mt = 0; mt < NMT; mt++) { ls2[mt][0] = 0.f; ls2[mt][1] = 0.f; }
        const float PSC = 0.015625f;   // 2^-6 storage scale
        __syncthreads();
        #pragma unroll
        for (int mt = 0; mt < NMT; mt++) {
            int rl = wm + mt*16 + gid;
            #pragma unroll
            for (int nt = 0; nt < 8; nt++) {
                int cl = wn + nt*8 + 2*tig;
                float e0 = expf(acc[mt][nt][0]);
                float e1 = expf(acc[mt][nt][1]);
                float e2 = expf(acc[mt][nt][2]);
                float e3 = expf(acc[mt][nt][3]);
                *(unsigned short*)&stg[rl*VST + cl]     = f2e4m3x2(e0*PSC, e1*PSC);
                *(unsigned short*)&stg[(rl+8)*VST + cl] = f2e4m3x2(e2*PSC, e3*PSC);
                ls2[mt][0] += e0 + e1;
                ls2[mt][1] += e2 + e3;
            }
        }
        #pragma unroll
        for (int mt = 0; mt < NMT; mt++)
            #pragma unroll
            for (int hlf = 0; hlf < 2; hlf++) {
                float v = ls2[mt][hlf];
                v += __shfl_xor_sync(0xffffffffu, v, 1);
                v += __shfl_xor_sync(0xffffffffu, v, 2);
                if (tig == 0) {
                    int row = m0 + wm + mt*16 + gid + hlf*8;
                    atomicAdd(&RS[(long)z*SEQ + row], v);
                }
            }
        __syncthreads();
        unsigned char* Pb = (unsigned char*)Cp;
        int rl = t >> 1, hf = t & 1;
        const uint4* src = (const uint4*)(stg + rl*VST + hf*64);
        uint4* dp = (uint4*)&Pb[(long)z*sC + (long)(m0 + rl)*Nc + n0 + hf*64];
        dp[0] = src[0]; dp[1] = src[1]; dp[2] = src[2]; dp[3] = src[3];
        return;
    }

    // EPI_OSCAT: o = acc * 64 / (rowsum * 16), scatter bf16 pairs
    {
        __nv_bfloat16* Ob = (__nv_bfloat16*)Cp;
        int b = z >> 3, h = z & 7;
        #pragma unroll
        for (int mt = 0; mt < NMT; mt++) {
            #pragma unroll
            for (int hlf = 0; hlf < 2; hlf++) {
                int row = m0 + wm + mt*16 + gid + hlf*8;
                float inv = 64.0f / (RS[(long)z*SEQ + row] * 16.0f);
                long base = ((long)(b*SEQ + row))*HID + h*DIM;
                #pragma unroll
                for (int nt = 0; nt < 8; nt++) {
                    int col = n0 + wn + nt*8 + 2*tig;
                    __nv_bfloat162 pk;
                    pk.x = __float2bfloat16(acc[mt][nt][2*hlf]   * inv);
                    pk.y = __float2bfloat16(acc[mt][nt][2*hlf+1] * inv);
                    *(__nv_bfloat162*)&Ob[base + col] = pk;
                }
            }
        }
    }
}

// ---------------- host orchestration ----------------
extern "C" void kernel_launch(void* const* d_in, const int* in_sizes, int n_in,
                              void* d_out, int out_size)
{
    const float* x_in  = (const float*)d_in[0];
    const float* ln1_g = (const float*)d_in[1];
    const float* ln1_b = (const float*)d_in[2];
    const float* qkv_w = (const float*)d_in[3];
    const float* qkv_b = (const float*)d_in[4];
    const float* proj_w= (const float*)d_in[5];
    const float* proj_b= (const float*)d_in[6];
    const float* ln2_g = (const float*)d_in[7];
    const float* ln2_b = (const float*)d_in[8];
    const float* w1    = (const float*)d_in[9];
    const float* b1    = (const float*)d_in[10];
    const float* w2    = (const float*)d_in[11];
    const float* b2    = (const float*)d_in[12];
    float* out = (float*)d_out;

    __nv_bfloat16 *h, *o, *mh, *rqkvw, *rprojw, *rw1, *rw2;
    unsigned char *q, *k, *v, *s;
    float *rs;
    cudaGetSymbolAddress((void**)&h,  g_h);
    cudaGetSymbolAddress((void**)&q,  g_q);
    cudaGetSymbolAddress((void**)&k,  g_k);
    cudaGetSymbolAddress((void**)&v,  g_v);
    cudaGetSymbolAddress((void**)&s,  g_s);
    cudaGetSymbolAddress((void**)&rs, g_rs);
    cudaGetSymbolAddress((void**)&o,  g_o);
    cudaGetSymbolAddress((void**)&mh, g_m);
    cudaGetSymbolAddress((void**)&rqkvw, g_qkvw);
    cudaGetSymbolAddress((void**)&rprojw, g_projw);
    cudaGetSymbolAddress((void**)&rw1, g_w1);
    cudaGetSymbolAddress((void**)&rw2, g_w2);

    cudaFuncSetAttribute(gemm_bf<EPI_QKV,2>,      cudaFuncAttributeMaxDynamicSharedMemorySize, GSMEM2);
    cudaFuncSetAttribute(gemm_bf<EPI_RES,1>,      cudaFuncAttributeMaxDynamicSharedMemorySize, GSMEM1);
    cudaFuncSetAttribute(gemm_bf<EPI_GELU,1>,     cudaFuncAttributeMaxDynamicSharedMemorySize, GSMEM1);
    cudaFuncSetAttribute(gemm_f8<EPI_EXPSTORE,2>, cudaFuncAttributeMaxDynamicSharedMemorySize, GSMEM2);
    cudaFuncSetAttribute(gemm_f8<EPI_OSCAT,1>,    cudaFuncAttributeMaxDynamicSharedMemorySize, GSMEM1);

    // preprocess weights
    dim3 tb(32, 8);
    wtrans_qkv_kernel<<<dim3(3*HID/32, DIM/32, LNUM), tb>>>(qkv_w, rqkvw);
    wtrans_kernel<<<dim3(DIM/32, HID/32, LNUM), tb>>>(proj_w, rprojw, HID, DIM);
    wtrans_kernel<<<dim3(MLP/32, DIM/32, LNUM), tb>>>(w1, rw1, DIM, MLP);
    wtrans_kernel<<<dim3(DIM/32, MLP/32, LNUM), tb>>>(w2, rw2, MLP, DIM);

    cudaMemcpyAsync(out, x_in, sizeof(float)*(size_t)ROWS*DIM, cudaMemcpyDeviceToDevice);

    for (int i = 0; i < LNUM; i++) {
        // LN1 -> h bf16
        ln_kernel<<<ROWS/8, 256>>>(out, ln1_g + i*DIM, ln1_b + i*DIM, h);
        // QKV: de-interleaved weights -> coalesced q/k/v fp8   (3072 CTAs)
        gemm_bf<EPI_QKV,2><<<dim3(3*HID/128, ROWS/128, 1), 256, GSMEM2>>>(
            h, rqkvw + (long)i*DIM*3*HID, qkv_b + (long)i*3*HID,
            q, k, v, nullptr, 3*HID, DIM, DIM, 0, 0, 0);
        // P = e4m3(exp(q k^T)/64) with fused fp32 rowsum       (4096 CTAs)
        cudaMemsetAsync(rs, 0, sizeof(float)*BH*SEQ);
        gemm_f8<EPI_EXPSTORE,2><<<dim3(SEQ/128, SEQ/128, BH), 256, GSMEM2>>>(
            q, k, s, rs, SEQ, DIM, DIM,
            (long)SEQ*DIM, (long)SEQ*DIM, (long)SEQ*SEQ);
        // o = P V * 64 / (rowsum*16), M=64 tiles               (2048 CTAs)
        gemm_f8<EPI_OSCAT,1><<<dim3(DIM/128, SEQ/64, BH), 256, GSMEM1>>>(
            s, v, o, rs, DIM, SEQ, SEQ,
            (long)SEQ*SEQ, (long)DIM*SEQ, 0);
        // x += o @ proj_w + proj_b : M=64 tiles, split-K=4     (1024 CTAs)
        gemm_bf<EPI_RES,1><<<dim3(DIM/128, ROWS/64, 4), 256, GSMEM1>>>(
            o, rprojw + (long)i*HID*DIM, proj_b + (long)i*DIM,
            out, nullptr, nullptr, nullptr, DIM, HID/4, HID, HID/4, HID/4, 0);
        // LN2 -> h bf16
        ln_kernel<<<ROWS/8, 256>>>(out, ln2_g + i*DIM, ln2_b + i*DIM, h);
        // mh = gelu(h @ w1 + b1), M=64 tiles                   (1024 CTAs)
        gemm_bf<EPI_GELU,1><<<dim3(MLP/128, ROWS/64, 1), 256, GSMEM1>>>(
            h, rw1 + (long)i*DIM*MLP, b1 + (long)i*MLP,
            mh, nullptr, nullptr, nullptr, MLP, DIM, DIM, 0, 0, 0);
        // x += mh @ w2 + b2 : M=64 tiles, split-K=4            (1024 CTAs)
        gemm_bf<EPI_RES,1><<<dim3(DIM/128, ROWS/64, 4), 256, GSMEM1>>>(
            mh, rw2 + (long)i*MLP*DIM, b2 + (long)i*DIM,
            out, nullptr, nullptr, nullptr, DIM, MLP/4, MLP, MLP/4, MLP/4, 0);
    }
}

// round 17
// speedup vs baseline: 1.0828x; 1.0828x over previous
#include <cuda_runtime.h>
#include <cuda_bf16.h>
#include <cuda_fp8.h>
#include <math.h>

#define LNUM 4
#define DIM 256
#define NH 8
#define MLP 1024
#define BATCH 8
#define SEQ 1024
#define HID 2048            // NH * DIM
#define ROWS (BATCH*SEQ)    // 8192
#define BH (BATCH*NH)       // 64

// ---------------- scratch (device globals; no allocation allowed) ----------------
__device__ __nv_bfloat16 g_h[ROWS*DIM];              // LN output
__device__ unsigned char g_q[BH*SEQ*DIM];            // q fp8 [b,h,n,d]
__device__ unsigned char g_k[BH*SEQ*DIM];            // k fp8 [b,h,n,d]
__device__ unsigned char g_v[BH*DIM*SEQ];            // v fp8 TRANSPOSED [b,h,d,n]
__device__ unsigned char g_s[(size_t)BH*SEQ*SEQ];    // P = e4m3(exp(s)/64) [bh][q][k]
__device__ float         g_rs[BH*SEQ];               // attention row sums (fp32, exact)
__device__ __nv_bfloat16 g_o[(size_t)ROWS*HID];      // attn out [b,n,h*d]
__device__ __nv_bfloat16 g_m[ROWS*MLP];              // mlp hidden
// transposed bf16 weights: [N][K]; qkv additionally de-interleaved (si-major)
__device__ __nv_bfloat16 g_qkvw[LNUM*DIM*3*HID];
__device__ __nv_bfloat16 g_projw[LNUM*HID*DIM];
__device__ __nv_bfloat16 g_w1[LNUM*DIM*MLP];
__device__ __nv_bfloat16 g_w2[LNUM*MLP*DIM];

// ---------------- weight preprocess: transpose [K][N] -> [N][K], cvt bf16 -------
__global__ void wtrans_kernel(const float* __restrict__ src, __nv_bfloat16* __restrict__ dst,
                              int K, int N)
{
    __shared__ float tile[32][33];
    long zo = (long)blockIdx.z * K * N;
    int k0 = blockIdx.y * 32, n0 = blockIdx.x * 32;
    for (int i = threadIdx.y; i < 32; i += 8)
        tile[i][threadIdx.x] = src[zo + (long)(k0 + i)*N + n0 + threadIdx.x];
    __syncthreads();
    int k = k0 + threadIdx.x;
    for (int i = threadIdx.y; i < 32; i += 8)
        dst[zo + (long)(n0 + i)*K + k] = __float2bfloat16(tile[threadIdx.x][i]);
}

// qkv variant: de-interleave columns: n_new = si*HID + h*DIM + dc
__global__ void wtrans_qkv_kernel(const float* __restrict__ src, __nv_bfloat16* __restrict__ dst)
{
    __shared__ float tile[32][33];
    const int K = DIM, N = 3*HID;
    long zo = (long)blockIdx.z * K * N;
    int k0 = blockIdx.y * 32, n0 = blockIdx.x * 32;
    for (int i = threadIdx.y; i < 32; i += 8)
        tile[i][threadIdx.x] = src[zo + (long)(k0 + i)*N + n0 + threadIdx.x];
    __syncthreads();
    int k = k0 + threadIdx.x;
    for (int i = threadIdx.y; i < 32; i += 8) {
        int n_old = n0 + i;
        int si = n_old % 3, dc = (n_old / 3) & (DIM - 1), h = n_old / (3*DIM);
        long n_new = (long)si*HID + h*DIM + dc;
        dst[zo + n_new*K + k] = __float2bfloat16(tile[threadIdx.x][i]);
    }
}

// ---------------- LayerNorm: warp per row, 8 rows/block, vectorized -------------
__global__ void ln_kernel(const float* __restrict__ x, const float* __restrict__ g,
                          const float* __restrict__ b, __nv_bfloat16* __restrict__ out)
{
    int lane = threadIdx.x & 31;
    long row = (long)blockIdx.x*8 + (threadIdx.x >> 5);
    const float4* xp = (const float4*)(x + row*DIM);
    float4 a0 = xp[lane*2], a1 = xp[lane*2 + 1];
    float s1 = a0.x + a0.y + a0.z + a0.w + a1.x + a1.y + a1.z + a1.w;
    float s2 = a0.x*a0.x + a0.y*a0.y + a0.z*a0.z + a0.w*a0.w
             + a1.x*a1.x + a1.y*a1.y + a1.z*a1.z + a1.w*a1.w;
    #pragma unroll
    for (int o = 16; o > 0; o >>= 1) {
        s1 += __shfl_xor_sync(0xffffffffu, s1, o);
        s2 += __shfl_xor_sync(0xffffffffu, s2, o);
    }
    float m = s1 * (1.0f/DIM);
    float rstd = rsqrtf(s2 * (1.0f/DIM) - m*m + 1e-5f);
    float4 g0 = ((const float4*)g)[lane*2], g1 = ((const float4*)g)[lane*2 + 1];
    float4 b0 = ((const float4*)b)[lane*2], b1 = ((const float4*)b)[lane*2 + 1];
    __nv_bfloat162 r[4];
    r[0].x = __float2bfloat16((a0.x - m)*rstd*g0.x + b0.x);
    r[0].y = __float2bfloat16((a0.y - m)*rstd*g0.y + b0.y);
    r[1].x = __float2bfloat16((a0.z - m)*rstd*g0.z + b0.z);
    r[1].y = __float2bfloat16((a0.w - m)*rstd*g0.w + b0.w);
    r[2].x = __float2bfloat16((a1.x - m)*rstd*g1.x + b1.x);
    r[2].y = __float2bfloat16((a1.y - m)*rstd*g1.y + b1.y);
    r[3].x = __float2bfloat16((a1.z - m)*rstd*g1.z + b1.z);
    r[3].y = __float2bfloat16((a1.w - m)*rstd*g1.w + b1.w);
    ((uint4*)(out + row*DIM))[lane] = *(uint4*)r;
}

// ---------------- MMA / cp.async / ldmatrix helpers ----------------
__device__ __forceinline__ void mma_bf16(float* d, unsigned a0, unsigned a1, unsigned a2,
                                         unsigned a3, unsigned b0, unsigned b1) {
    asm volatile(
        "mma.sync.aligned.m16n8k16.row.col.f32.bf16.bf16.f32 "
        "{%0,%1,%2,%3}, {%4,%5,%6,%7}, {%8,%9}, {%0,%1,%2,%3};"
        : "+f"(d[0]), "+f"(d[1]), "+f"(d[2]), "+f"(d[3])
        : "r"(a0), "r"(a1), "r"(a2), "r"(a3), "r"(b0), "r"(b1));
}
__device__ __forceinline__ void mma_e4m3(float* d, unsigned a0, unsigned a1, unsigned a2,
                                         unsigned a3, unsigned b0, unsigned b1) {
    asm volatile(
        "mma.sync.aligned.m16n8k32.row.col.f32.e4m3.e4m3.f32 "
        "{%0,%1,%2,%3}, {%4,%5,%6,%7}, {%8,%9}, {%0,%1,%2,%3};"
        : "+f"(d[0]), "+f"(d[1]), "+f"(d[2]), "+f"(d[3])
        : "r"(a0), "r"(a1), "r"(a2), "r"(a3), "r"(b0), "r"(b1));
}
__device__ __forceinline__ void cpa16(unsigned d, const void* s) {
    asm volatile("cp.async.ca.shared.global [%0], [%1], 16;" :: "r"(d), "l"(s));
}
__device__ __forceinline__ void ldsm_x4(unsigned* r, unsigned a) {
    asm volatile("ldmatrix.sync.aligned.m8n8.x4.shared.b16 {%0,%1,%2,%3}, [%4];"
        : "=r"(r[0]), "=r"(r[1]), "=r"(r[2]), "=r"(r[3]) : "r"(a));
}
__device__ __forceinline__ unsigned short f2e4m3x2(float lo, float hi) {
    unsigned short r;
    asm("cvt.rn.satfinite.e4m3x2.f32 %0, %1, %2;" : "=h"(r) : "f"(hi), "f"(lo));
    return r;
}
__device__ __forceinline__ unsigned char f2e4m3(float v) {
    return (unsigned char)(f2e4m3x2(v, 0.f) & 0xFF);
}

enum { EPI_QKV = 0, EPI_EXPSTORE = 1, EPI_OSCAT = 2, EPI_RES = 3, EPI_GELU = 4 };

#define BKS 80             // bytes per staged row (64B data + 16B pad): LDSM conflict-free
#define ASTG (128*BKS)     // one stage of one operand (10240 B)
#define NSTG 3
#define GSMEM (2*NSTG*ASTG)   // 61440 B dynamic smem
#define VST 144            // fp8 epilogue staging row stride (16-aligned)

// ================================================================================
// bf16 TC GEMM (dense path): R10 mainloop + fully coalesced epilogues.
// ================================================================================
template<int EPI>
__global__ __launch_bounds__(256, 2)
void gemm_bf(const __nv_bfloat16* __restrict__ A, const __nv_bfloat16* __restrict__ Bm,
             const float* __restrict__ bias, void* __restrict__ Cp,
             void* __restrict__ P1, void* __restrict__ P2, float* __restrict__ RS,
             int Nc, int K, int ldk, long sA, long sB, long sC)
{
    extern __shared__ char dsm[];

    int z  = blockIdx.z;
    int m0 = blockIdx.y * 128;
    int n0 = blockIdx.x * 128;
    int t    = threadIdx.x;
    int lane = t & 31;
    int warp = t >> 5;
    int wm = (warp >> 1) * 32;
    int wn = (warp & 1) * 64;
    int gid = lane >> 2;
    int tig = lane & 3;

    int lr = t >> 1;
    const __nv_bfloat16* apg = A + z*sA + (long)(m0 + lr)*ldk + (t & 1)*16;
    const __nv_bfloat16* bpg = Bm + z*sB + (long)(n0 + lr)*ldk + (t & 1)*16;
    unsigned asb = (unsigned)__cvta_generic_to_shared(dsm);
    unsigned bsb = asb + NSTG*ASTG;
    unsigned adl = asb + (unsigned)(lr*BKS + (t & 1)*32);
    unsigned bdl = bsb + (unsigned)(lr*BKS + (t & 1)*32);

    int lm = lane >> 3, ls = lane & 7;
    unsigned lro = (unsigned)(((lm & 1)*8 + ls)*BKS + (lm >> 1)*16);
    unsigned abase = asb + (unsigned)(wm*BKS) + lro;
    unsigned bbase = bsb + (unsigned)(wn*BKS) + lro;

    float acc[2][8][4];
    #pragma unroll
    for (int mt = 0; mt < 2; mt++)
        #pragma unroll
        for (int nt = 0; nt < 8; nt++)
            #pragma unroll
            for (int p = 0; p < 4; p++) acc[mt][nt][p] = 0.f;

    int niter = K / 32;
    #pragma unroll
    for (int pi = 0; pi < 2; pi++) {
        int k0 = pi * 32;
        unsigned ao = (unsigned)(pi*ASTG);
        cpa16(adl + ao, apg + k0);  cpa16(adl + ao + 16, apg + k0 + 8);
        cpa16(bdl + ao, bpg + k0);  cpa16(bdl + ao + 16, bpg + k0 + 8);
        asm volatile("cp.async.commit_group;");
    }

    int st = 0;
    for (int iter = 0; iter < niter; iter++) {
        if (iter + 1 < niter) asm volatile("cp.async.wait_group 1;");
        else                  asm volatile("cp.async.wait_group 0;");
        __syncthreads();

        if (iter + 2 < niter) {
            int k0 = (iter + 2) * 32;
            int ws = st + 2; if (ws >= NSTG) ws -= NSTG;
            unsigned ao = (unsigned)(ws*ASTG);
            cpa16(adl + ao, apg + k0);  cpa16(adl + ao + 16, apg + k0 + 8);
            cpa16(bdl + ao, bpg + k0);  cpa16(bdl + ao + 16, bpg + k0 + 8);
            asm volatile("cp.async.commit_group;");
        }

        unsigned so = (unsigned)(st*ASTG);
        #pragma unroll
        for (int kh = 0; kh < 2; kh++) {
            unsigned af[2][4], bq[4][4];
            #pragma unroll
            for (int mt = 0; mt < 2; mt++)
                ldsm_x4(af[mt], abase + so + (unsigned)(mt*16*BKS + kh*32));
            #pragma unroll
            for (int p = 0; p < 4; p++)
                ldsm_x4(bq[p], bbase + so + (unsigned)(p*16*BKS + kh*32));
            #pragma unroll
            for (int mt = 0; mt < 2; mt++)
                #pragma unroll
                for (int p = 0; p < 4; p++) {
                    mma_bf16(acc[mt][2*p],   af[mt][0], af[mt][1], af[mt][2], af[mt][3],
                             bq[p][0], bq[p][2]);
                    mma_bf16(acc[mt][2*p+1], af[mt][0], af[mt][1], af[mt][2], af[mt][3],
                             bq[p][1], bq[p][3]);
                }
        }
        st++; if (st >= NSTG) st = 0;
    }

    // ---------------- epilogues ----------------
    if (EPI == EPI_QKV) {
        // de-interleaved layout: this block is one (si, head, dc-half) slab
        int si  = n0 / HID;
        int hh  = (n0 % HID) / DIM;
        int dc0 = n0 % DIM;
        int b_ = m0 >> 10;
        long bh = (long)b_*NH + hh;
        unsigned char* stg = (unsigned char*)dsm;
        __syncthreads();                 // mainloop smem now reusable
        if (si < 2) {
            // q/k: stage row-major [n_local][dc_local], write 64B runs
            #pragma unroll
            for (int mt = 0; mt < 2; mt++) {
                int rl = wm + mt*16 + gid;
                #pragma unroll
                for (int nt = 0; nt < 8; nt++) {
                    int cl = wn + nt*8 + 2*tig;
                    int dc = dc0 + cl;
                    float bb0 = bias[hh*3*DIM + dc*3 + si];
                    float bb1 = bias[hh*3*DIM + (dc+1)*3 + si];
                    *(unsigned short*)&stg[rl*VST + cl] =
                        f2e4m3x2(acc[mt][nt][0] + bb0, acc[mt][nt][1] + bb1);
                    *(unsigned short*)&stg[(rl+8)*VST + cl] =
                        f2e4m3x2(acc[mt][nt][2] + bb0, acc[mt][nt][3] + bb1);
                }
            }
            __syncthreads();
            unsigned char* dst = (unsigned char*)((si == 0) ? Cp : P1);
            int rl = t >> 1, hf = t & 1;
            int n1 = (m0 + rl) & (SEQ - 1);
            const uint4* src = (const uint4*)(stg + rl*VST + hf*64);
            uint4* dq = (uint4*)&dst[(bh*SEQ + n1)*DIM + dc0 + hf*64];
            dq[0] = src[0]; dq[1] = src[1]; dq[2] = src[2]; dq[3] = src[3];
        } else {
            // v: stage [dc][n] transpose, write coalesced 64B runs
            #pragma unroll
            for (int mt = 0; mt < 2; mt++) {
                int rl = wm + mt*16 + gid;
                #pragma unroll
                for (int nt = 0; nt < 8; nt++) {
                    int cl = wn + nt*8 + 2*tig;
                    int dc = dc0 + cl;
                    float bb0 = bias[hh*3*DIM + dc*3 + 2];
                    float bb1 = bias[hh*3*DIM + (dc+1)*3 + 2];
                    stg[cl*VST + rl]         = f2e4m3(acc[mt][nt][0] + bb0);
                    stg[(cl+1)*VST + rl]     = f2e4m3(acc[mt][nt][1] + bb1);
                    stg[cl*VST + rl + 8]     = f2e4m3(acc[mt][nt][2] + bb0);
                    stg[(cl+1)*VST + rl + 8] = f2e4m3(acc[mt][nt][3] + bb1);
                }
            }
            __syncthreads();
            int nb = m0 & (SEQ - 1);
            int dcr = t >> 1, hf = t & 1;
            const uint4* src = (const uint4*)(stg + dcr*VST + hf*64);
            uint4* dstv = (uint4*)&((unsigned char*)P2)[(bh*DIM + dc0 + dcr)*SEQ + nb + hf*64];
            dstv[0] = src[0]; dstv[1] = src[1]; dstv[2] = src[2]; dstv[3] = src[3];
        }
        return;
    }

    #pragma unroll
    for (int mt = 0; mt < 2; mt++) {
        #pragma unroll
        for (int nt = 0; nt < 8; nt++) {
            int r0 = m0 + wm + mt*16 + gid;
            int col = n0 + wn + nt*8 + 2*tig;
            if (EPI == EPI_RES) {
                #pragma unroll
                for (int p = 0; p < 4; p++) {
                    int row = r0 + ((p >= 2) ? 8 : 0);
                    int cc = col + (p & 1);
                    float add = acc[mt][nt][p] + ((z == 0) ? bias[cc] : 0.f);
                    atomicAdd(&((float*)Cp)[(long)row*Nc + cc], add);
                }
            } else {   // EPI_GELU: packed bf162 stores
                float u0 = acc[mt][nt][0] + bias[col];
                float u1 = acc[mt][nt][1] + bias[col+1];
                float u2 = acc[mt][nt][2] + bias[col];
                float u3 = acc[mt][nt][3] + bias[col+1];
                __nv_bfloat162 lo, hi;
                lo.x = __float2bfloat16(0.5f*u0*(1.0f + erff(u0*0.70710678118654752f)));
                lo.y = __float2bfloat16(0.5f*u1*(1.0f + erff(u1*0.70710678118654752f)));
                hi.x = __float2bfloat16(0.5f*u2*(1.0f + erff(u2*0.70710678118654752f)));
                hi.y = __float2bfloat16(0.5f*u3*(1.0f + erff(u3*0.70710678118654752f)));
                *(__nv_bfloat162*)&((__nv_bfloat16*)Cp)[(long)r0*Nc + col]     = lo;
                *(__nv_bfloat162*)&((__nv_bfloat16*)Cp)[(long)(r0+8)*Nc + col] = hi;
            }
        }
    }
}

// ================================================================================
// FP8 TC GEMM (attention path): R13 mainloop + coalesced EXPSTORE epilogue.
// ================================================================================
template<int EPI>
__global__ __launch_bounds__(256, 2)
void gemm_f8(const unsigned char* __restrict__ A, const unsigned char* __restrict__ Bm,
             void* __restrict__ Cp, float* __restrict__ RS,
             int Nc, int K, int ldk, long sA, long sB, long sC)
{
    extern __shared__ char dsm[];

    int z  = blockIdx.z;
    int m0 = blockIdx.y * 128;
    int n0 = blockIdx.x * 128;
    int t    = threadIdx.x;
    int lane = t & 31;
    int warp = t >> 5;
    int wm = (warp >> 1) * 32;
    int wn = (warp & 1) * 64;
    int gid = lane >> 2;
    int tig = lane & 3;

    int lr = t >> 1;
    const unsigned char* apg = A + z*sA + (long)(m0 + lr)*ldk + (t & 1)*32;
    const unsigned char* bpg = Bm + z*sB + (long)(n0 + lr)*ldk + (t & 1)*32;
    unsigned asb = (unsigned)__cvta_generic_to_shared(dsm);
    unsigned bsb = asb + NSTG*ASTG;
    unsigned adl = asb + (unsigned)(lr*BKS + (t & 1)*32);
    unsigned bdl = bsb + (unsigned)(lr*BKS + (t & 1)*32);

    int lm = lane >> 3, ls = lane & 7;
    unsigned lro = (unsigned)(((lm & 1)*8 + ls)*BKS + (lm >> 1)*16);
    unsigned abase = asb + (unsigned)(wm*BKS) + lro;
    unsigned bbase = bsb + (unsigned)(wn*BKS) + lro;

    float acc[2][8][4];
    #pragma unroll
    for (int mt = 0; mt < 2; mt++)
        #pragma unroll
        for (int nt = 0; nt < 8; nt++)
            #pragma unroll
            for (int p = 0; p < 4; p++) acc[mt][nt][p] = 0.f;

    int niter = K / 64;
    #pragma unroll
    for (int pi = 0; pi < 2; pi++) {
        int k0 = pi * 64;
        unsigned ao = (unsigned)(pi*ASTG);
        cpa16(adl + ao, apg + k0);  cpa16(adl + ao + 16, apg + k0 + 16);
        cpa16(bdl + ao, bpg + k0);  cpa16(bdl + ao + 16, bpg + k0 + 16);
        asm volatile("cp.async.commit_group;");
    }

    int st = 0;
    for (int iter = 0; iter < niter; iter++) {
        if (iter + 1 < niter) asm volatile("cp.async.wait_group 1;");
        else                  asm volatile("cp.async.wait_group 0;");
        __syncthreads();

        if (iter + 2 < niter) {
            int k0 = (iter + 2) * 64;
            int ws = st + 2; if (ws >= NSTG) ws -= NSTG;
            unsigned ao = (unsigned)(ws*ASTG);
            cpa16(adl + ao, apg + k0);  cpa16(adl + ao + 16, apg + k0 + 16);
            cpa16(bdl + ao, bpg + k0);  cpa16(bdl + ao + 16, bpg + k0 + 16);
            asm volatile("cp.async.commit_group;");
        }

        unsigned so = (unsigned)(st*ASTG);
        #pragma unroll
        for (int kh = 0; kh < 2; kh++) {
            unsigned af[2][4], bq[4][4];
            #pragma unroll
            for (int mt = 0; mt < 2; mt++)
                ldsm_x4(af[mt], abase + so + (unsigned)(mt*16*BKS + kh*32));
            #pragma unroll
            for (int p = 0; p < 4; p++)
                ldsm_x4(bq[p], bbase + so + (unsigned)(p*16*BKS + kh*32));
            #pragma unroll
            for (int mt = 0; mt < 2; mt++)
                #pragma unroll
                for (int p = 0; p < 4; p++) {
                    mma_e4m3(acc[mt][2*p],   af[mt][0], af[mt][1], af[mt][2], af[mt][3],
                             bq[p][0], bq[p][2]);
                    mma_e4m3(acc[mt][2*p+1], af[mt][0], af[mt][1], af[mt][2], af[mt][3],
                             bq[p][1], bq[p][3]);
                }
        }
        st++; if (st >= NSTG) st = 0;
    }

    if (EPI == EPI_EXPSTORE) {
        unsigned char* stg = (unsigned char*)dsm;
        float ls2[2][2] = {{0.f, 0.f}, {0.f, 0.f}};
        const float PSC = 0.015625f;   // 2^-6 storage scale
        __syncthreads();               // mainloop smem now reusable
        #pragma unroll
        for (int mt = 0; mt < 2; mt++) {
            int rl = wm + mt*16 + gid;
            #pragma unroll
            for (int nt = 0; nt < 8; nt++) {
                int cl = wn + nt*8 + 2*tig;
                float e0 = expf(acc[mt][nt][0]);
                float e1 = expf(acc[mt][nt][1]);
                float e2 = expf(acc[mt][nt][2]);
                float e3 = expf(acc[mt][nt][3]);
                *(unsigned short*)&stg[rl*VST + cl]     = f2e4m3x2(e0*PSC, e1*PSC);
                *(unsigned short*)&stg[(rl+8)*VST + cl] = f2e4m3x2(e2*PSC, e3*PSC);
                ls2[mt][0] += e0 + e1;
                ls2[mt][1] += e2 + e3;
            }
        }
        #pragma unroll
        for (int mt = 0; mt < 2; mt++)
            #pragma unroll
            for (int hlf = 0; hlf < 2; hlf++) {
                float v = ls2[mt][hlf];
                v += __shfl_xor_sync(0xffffffffu, v, 1);
                v += __shfl_xor_sync(0xffffffffu, v, 2);
                if (tig == 0) {
                    int row = m0 + wm + mt*16 + gid + hlf*8;
                    atomicAdd(&RS[(long)z*SEQ + row], v);
                }
            }
        __syncthreads();
        unsigned char* Pb = (unsigned char*)Cp;
        int rl = t >> 1, hf = t & 1;
        const uint4* src = (const uint4*)(stg + rl*VST + hf*64);
        uint4* dp = (uint4*)&Pb[(long)z*sC + (long)(m0 + rl)*Nc + n0 + hf*64];
        dp[0] = src[0]; dp[1] = src[1]; dp[2] = src[2]; dp[3] = src[3];
        return;
    }

    // EPI_OSCAT: o = acc * 64 / (rowsum * 16), scatter bf16 pairs
    {
        __nv_bfloat16* Ob = (__nv_bfloat16*)Cp;
        int b = z >> 3, h = z & 7;
        #pragma unroll
        for (int mt = 0; mt < 2; mt++) {
            #pragma unroll
            for (int hlf = 0; hlf < 2; hlf++) {
                int row = m0 + wm + mt*16 + gid + hlf*8;
                float inv = 64.0f / (RS[(long)z*SEQ + row] * 16.0f);
                long base = ((long)(b*SEQ + row))*HID + h*DIM;
                #pragma unroll
                for (int nt = 0; nt < 8; nt++) {
                    int col = n0 + wn + nt*8 + 2*tig;
                    __nv_bfloat162 pk;
                    pk.x = __float2bfloat16(acc[mt][nt][2*hlf]   * inv);
                    pk.y = __float2bfloat16(acc[mt][nt][2*hlf+1] * inv);
                    *(__nv_bfloat162*)&Ob[base + col] = pk;
                }
            }
        }
    }
}

// ---------------- host orchestration ----------------
extern "C" void kernel_launch(void* const* d_in, const int* in_sizes, int n_in,
                              void* d_out, int out_size)
{
    const float* x_in  = (const float*)d_in[0];
    const float* ln1_g = (const float*)d_in[1];
    const float* ln1_b = (const float*)d_in[2];
    const float* qkv_w = (const float*)d_in[3];
    const float* qkv_b = (const float*)d_in[4];
    const float* proj_w= (const float*)d_in[5];
    const float* proj_b= (const float*)d_in[6];
    const float* ln2_g = (const float*)d_in[7];
    const float* ln2_b = (const float*)d_in[8];
    const float* w1    = (const float*)d_in[9];
    const float* b1    = (const float*)d_in[10];
    const float* w2    = (const float*)d_in[11];
    const float* b2    = (const float*)d_in[12];
    float* out = (float*)d_out;

    __nv_bfloat16 *h, *o, *mh, *rqkvw, *rprojw, *rw1, *rw2;
    unsigned char *q, *k, *v, *s;
    float *rs;
    cudaGetSymbolAddress((void**)&h,  g_h);
    cudaGetSymbolAddress((void**)&q,  g_q);
    cudaGetSymbolAddress((void**)&k,  g_k);
    cudaGetSymbolAddress((void**)&v,  g_v);
    cudaGetSymbolAddress((void**)&s,  g_s);
    cudaGetSymbolAddress((void**)&rs, g_rs);
    cudaGetSymbolAddress((void**)&o,  g_o);
    cudaGetSymbolAddress((void**)&mh, g_m);
    cudaGetSymbolAddress((void**)&rqkvw, g_qkvw);
    cudaGetSymbolAddress((void**)&rprojw, g_projw);
    cudaGetSymbolAddress((void**)&rw1, g_w1);
    cudaGetSymbolAddress((void**)&rw2, g_w2);

    cudaFuncSetAttribute(gemm_bf<EPI_QKV>,      cudaFuncAttributeMaxDynamicSharedMemorySize, GSMEM);
    cudaFuncSetAttribute(gemm_bf<EPI_RES>,      cudaFuncAttributeMaxDynamicSharedMemorySize, GSMEM);
    cudaFuncSetAttribute(gemm_bf<EPI_GELU>,     cudaFuncAttributeMaxDynamicSharedMemorySize, GSMEM);
    cudaFuncSetAttribute(gemm_f8<EPI_EXPSTORE>, cudaFuncAttributeMaxDynamicSharedMemorySize, GSMEM);
    cudaFuncSetAttribute(gemm_f8<EPI_OSCAT>,    cudaFuncAttributeMaxDynamicSharedMemorySize, GSMEM);

    // preprocess weights
    dim3 tb(32, 8);
    wtrans_qkv_kernel<<<dim3(3*HID/32, DIM/32, LNUM), tb>>>(qkv_w, rqkvw);
    wtrans_kernel<<<dim3(DIM/32, HID/32, LNUM), tb>>>(proj_w, rprojw, HID, DIM);
    wtrans_kernel<<<dim3(MLP/32, DIM/32, LNUM), tb>>>(w1, rw1, DIM, MLP);
    wtrans_kernel<<<dim3(DIM/32, MLP/32, LNUM), tb>>>(w2, rw2, MLP, DIM);

    cudaMemcpyAsync(out, x_in, sizeof(float)*(size_t)ROWS*DIM, cudaMemcpyDeviceToDevice);

    for (int i = 0; i < LNUM; i++) {
        // LN1 -> h bf16
        ln_kernel<<<ROWS/8, 256>>>(out, ln1_g + i*DIM, ln1_b + i*DIM, h);
        // QKV: de-interleaved weights -> coalesced q/k/v fp8
        gemm_bf<EPI_QKV><<<dim3(3*HID/128, ROWS/128, 1), 256, GSMEM>>>(
            h, rqkvw + (long)i*DIM*3*HID, qkv_b + (long)i*3*HID,
            q, k, v, nullptr, 3*HID, DIM, DIM, 0, 0, 0);
        // P = e4m3(exp(q k^T)/64) with fused fp32 rowsum (fp8 MMA, K=256)
        cudaMemsetAsync(rs, 0, sizeof(float)*BH*SEQ);
        gemm_f8<EPI_EXPSTORE><<<dim3(SEQ/128, SEQ/128, BH), 256, GSMEM>>>(
            q, k, s, rs, SEQ, DIM, DIM,
            (long)SEQ*DIM, (long)SEQ*DIM, (long)SEQ*SEQ);
        // o = P V * 64 / (rowsum*16) (fp8 MMA, K=1024), scatter bf16 [b,n,h*d]
        gemm_f8<EPI_OSCAT><<<dim3(DIM/128, SEQ/128, BH), 256, GSMEM>>>(
            s, v, o, rs, DIM, SEQ, SEQ,
            (long)SEQ*SEQ, (long)DIM*SEQ, 0);
        // x += o @ proj_w + proj_b : split-K=2, fp32 atomic residual
        gemm_bf<EPI_RES><<<dim3(DIM/128, ROWS/128, 2), 256, GSMEM>>>(
            o, rprojw + (long)i*HID*DIM, proj_b + (long)i*DIM,
            out, nullptr, nullptr, nullptr, DIM, HID/2, HID, HID/2, HID/2, 0);
        // LN2 -> h bf16
        ln_kernel<<<ROWS/8, 256>>>(out, ln2_g + i*DIM, ln2_b + i*DIM, h);
        // mh = gelu(h @ w1 + b1) bf16
        gemm_bf<EPI_GELU><<<dim3(MLP/128, ROWS/128, 1), 256, GSMEM>>>(
            h, rw1 + (long)i*DIM*MLP, b1 + (long)i*MLP,
            mh, nullptr, nullptr, nullptr, MLP, DIM, DIM, 0, 0, 0);
        // x += mh @ w2 + b2 : split-K=2, fp32 atomic residual
        gemm_bf<EPI_RES><<<dim3(DIM/128, ROWS/128, 2), 256, GSMEM>>>(
            mh, rw2 + (long)i*MLP*DIM, b2 + (long)i*DIM,
            out, nullptr, nullptr, nullptr, DIM, MLP/2, MLP, MLP/2, MLP/2, 0);
    }
}